// round 11
// baseline (speedup 1.0000x reference)
#include <cuda_runtime.h>
#include <cstdint>
#include <cfloat>

#define NEG_SLOPE 0.01f

constexpr int Vv = 32, Fv = 16, Hv = 64;
constexpr int NG = 32 * 512;         // 16384 groups
constexpr int GPP = 4;               // groups per pass
constexpr int NPASS = NG / GPP;      // 4096
constexpr int THREADS = 256;
constexpr int STRIDE = 68;           // padded activation row stride (conflict-free LDS.128)
constexpr int GRID = 296;            // 2 blocks/SM * 148 SMs

// Out-halves (cols 0..63) of W2/W3 live in constant memory: [h][64] contiguous.
__constant__ float cW2h[4096];
__constant__ float cW3h[4096];

// Shared float layout (109312 B -> 2 blocks/SM):
constexpr int OFF_W1   = 0;        // 1024
constexpr int OFF_W2P  = 1024;     // 4096  pool-half W2 [h*64+jj] (col 64+jj)
constexpr int OFF_W3P  = 5120;     // 4096
constexpr int OFF_B1   = 9216;     // 64
constexpr int OFF_B2   = 9280;     // 64
constexpr int OFF_B3   = 9344;     // 64
constexpr int OFF_PL1  = 9408;     // 256 [GPP][64]
constexpr int OFF_PL2  = 9664;     // 256
constexpr int OFF_BUFA = 9920;     // 8704 [GPP][32][STRIDE]
constexpr int OFF_BUFB = 18624;    // 8704
constexpr int SMEM_FLOATS = 27328;
constexpr int SMEM_BYTES  = SMEM_FLOATS * 4;   // 109312

__device__ __forceinline__ float warp_max_f32(float v) {
    #pragma unroll
    for (int o = 16; o >= 1; o >>= 1)
        v = fmaxf(v, __shfl_xor_sync(0xffffffffu, v, o));
    return v;
}
__device__ __forceinline__ float warp_sum_f32(float v) {
    #pragma unroll
    for (int o = 16; o >= 1; o >>= 1)
        v += __shfl_xor_sync(0xffffffffu, v, o);
    return v;
}
__device__ __forceinline__ void ffma2(unsigned long long& d, unsigned long long a, unsigned long long b) {
    asm("fma.rn.f32x2 %0, %1, %2, %0;" : "+l"(d) : "l"(a), "l"(b));
}
__device__ __forceinline__ unsigned long long pack2(float lo, float hi) {
    unsigned long long r;
    asm("mov.b64 %0, {%1, %2};" : "=l"(r) : "f"(lo), "f"(hi));
    return r;
}
__device__ __forceinline__ float unpack_sum(unsigned long long v) {
    float lo, hi;
    asm("mov.b64 {%0, %1}, %2;" : "=f"(lo), "=f"(hi) : "l"(v));
    return lo + hi;
}

// One 4-hh sweep of a 64-j dot-product layer, f32x2-packed along j.
// CW: constant array (out-half, [h*64+j]); BUF: smem activation base.
#define JSWEEP(CW, BUF, hoff, acc2, cinit)                                        \
    {                                                                             \
        _Pragma("unroll")                                                         \
        for (int gi = 0; gi < GPP; gi++)                                          \
            _Pragma("unroll")                                                     \
            for (int hh = 0; hh < 4; hh++)                                        \
                acc2[gi][hh] = pack2(cinit[gi][hh + hoff], 0.0f);                 \
        _Pragma("unroll 4")                                                       \
        for (int j = 0; j < 64; j += 4) {                                         \
            ulonglong2 wv[4];                                                     \
            _Pragma("unroll")                                                     \
            for (int hh = 0; hh < 4; hh++)                                        \
                wv[hh] = *(const ulonglong2*)&CW[(hbase + hoff + hh) * 64 + j];   \
            _Pragma("unroll")                                                     \
            for (int gi = 0; gi < GPP; gi++) {                                    \
                ulonglong2 a2 = *(const ulonglong2*)(BUF + gi * (Vv * STRIDE) +   \
                                                     lane * STRIDE + j);          \
                _Pragma("unroll")                                                 \
                for (int hh = 0; hh < 4; hh++) {                                  \
                    ffma2(acc2[gi][hh], a2.x, wv[hh].x);                          \
                    ffma2(acc2[gi][hh], a2.y, wv[hh].y);                          \
                }                                                                 \
            }                                                                     \
        }                                                                         \
    }

__global__ __launch_bounds__(THREADS, 2)
void fused_mlp_pool_kernel(const float* __restrict__ x,
                           const void*  __restrict__ maskp,
                           const float* __restrict__ W1,
                           const float* __restrict__ b1,
                           const float* __restrict__ W2,
                           const float* __restrict__ b2,
                           const float* __restrict__ W3,
                           const float* __restrict__ b3,
                           float* __restrict__ out)
{
    extern __shared__ float sm[];
    float* W1s  = sm + OFF_W1;
    float* W2ps = sm + OFF_W2P;
    float* W3ps = sm + OFF_W3P;
    float* b1s  = sm + OFF_B1;
    float* b2s  = sm + OFF_B2;
    float* b3s  = sm + OFF_B3;
    float* pl1  = sm + OFF_PL1;
    float* pl2  = sm + OFF_PL2;
    float* bufA = sm + OFF_BUFA;
    float* bufB = sm + OFF_BUFB;

    const int tid  = threadIdx.x;
    const int lane = tid & 31;      // = v
    const int warp = tid >> 5;      // 0..7
    const int hbase = warp * 8;

    // ---- stage W1 + pool-halves of W2/W3 + biases into shared ----
    for (int i = tid; i < 1024; i += THREADS) W1s[i] = W1[i];
    for (int i = tid; i < 4096; i += THREADS) {
        int h = i >> 6, jj = i & 63;
        W2ps[i] = W2[h * 128 + 64 + jj];
        W3ps[i] = W3[h * 128 + 64 + jj];
    }
    if (tid < 64) { b1s[tid] = b1[tid]; b2s[tid] = b2[tid]; b3s[tid] = b3[tid]; }

    // ---- detect mask encoding (bool-u8 / int32 / float32) ----
    __shared__ int s_flags[4];
    if (tid < 4) s_flags[tid] = 0;
    __syncthreads();
    {
        int f0 = 0, f1 = 0, f23 = 0;
        const unsigned char* mb = (const unsigned char*)maskp;
        #pragma unroll
        for (int i = 0; i < 16; i++) {
            int idx = tid * 16 + i;
            unsigned char c = mb[idx];
            if (c) { int m = idx & 3; if (m == 0) f0 = 1; else if (m == 1) f1 = 1; else f23 = 1; }
        }
        if (f0)  atomicOr(&s_flags[0], 1);
        if (f1)  atomicOr(&s_flags[1], 1);
        if (f23) atomicOr(&s_flags[2], 1);
    }
    __syncthreads();
    const int fmt = s_flags[1] ? 1 : (s_flags[0] ? 0 : (s_flags[2] ? 2 : 0));

    for (int pass = blockIdx.x; pass < NPASS; pass += gridDim.x) {
        const int g0 = pass * GPP;

        bool valid[GPP], anyv[GPP];
        #pragma unroll
        for (int gi = 0; gi < GPP; gi++) {
            const int midx = (g0 + gi) * Vv + lane;
            bool v;
            if (fmt == 1)      v = ((const unsigned char*)maskp)[midx] != 0;
            else if (fmt == 0) v = ((const int*)maskp)[midx] != 0;
            else               v = ((const float*)maskp)[midx] != 0.0f;
            valid[gi] = v;
            anyv[gi]  = __ballot_sync(0xffffffffu, v) != 0;
        }

        float4 xr[GPP][4];
        #pragma unroll
        for (int gi = 0; gi < GPP; gi++) {
            const float4* xp = (const float4*)(x + ((size_t)(g0 + gi) * Vv + lane) * Fv);
            xr[gi][0] = xp[0]; xr[gi][1] = xp[1]; xr[gi][2] = xp[2]; xr[gi][3] = xp[3];
        }

        // ================= Layer 1: 16 -> 64 (scalar, smem weights) =================
        float acc1[GPP][8];
        #pragma unroll 2
        for (int hh = 0; hh < 8; hh++) {
            const float4* w = (const float4*)(W1s + (hbase + hh) * 16);
            float4 w0 = w[0], w1 = w[1], w2 = w[2], w3 = w[3];
            const float bb = b1s[hbase + hh];
            #pragma unroll
            for (int gi = 0; gi < GPP; gi++) {
                float s = bb;
                s = fmaf(xr[gi][0].x, w0.x, s); s = fmaf(xr[gi][0].y, w0.y, s);
                s = fmaf(xr[gi][0].z, w0.z, s); s = fmaf(xr[gi][0].w, w0.w, s);
                s = fmaf(xr[gi][1].x, w1.x, s); s = fmaf(xr[gi][1].y, w1.y, s);
                s = fmaf(xr[gi][1].z, w1.z, s); s = fmaf(xr[gi][1].w, w1.w, s);
                s = fmaf(xr[gi][2].x, w2.x, s); s = fmaf(xr[gi][2].y, w2.y, s);
                s = fmaf(xr[gi][2].z, w2.z, s); s = fmaf(xr[gi][2].w, w2.w, s);
                s = fmaf(xr[gi][3].x, w3.x, s); s = fmaf(xr[gi][3].y, w3.y, s);
                s = fmaf(xr[gi][3].z, w3.z, s); s = fmaf(xr[gi][3].w, w3.w, s);
                acc1[gi][hh] = s;
            }
        }
        #pragma unroll
        for (int gi = 0; gi < GPP; gi++) {
            float o[8], m[8];
            #pragma unroll
            for (int hh = 0; hh < 8; hh++) {
                float r = acc1[gi][hh] > 0.0f ? acc1[gi][hh] : NEG_SLOPE * acc1[gi][hh];
                o[hh] = valid[gi] ? r : 0.0f;
                m[hh] = warp_max_f32(valid[gi] ? r : -FLT_MAX);
            }
            float* row = bufA + gi * (Vv * STRIDE) + lane * STRIDE + hbase;
            *(float4*)(row)     = make_float4(o[0], o[1], o[2], o[3]);
            *(float4*)(row + 4) = make_float4(o[4], o[5], o[6], o[7]);
            if (lane == 0) {
                float* pp = pl1 + gi * 64 + hbase;
                *(float4*)(pp)     = make_float4(anyv[gi] ? m[0] : 0.0f, anyv[gi] ? m[1] : 0.0f,
                                                 anyv[gi] ? m[2] : 0.0f, anyv[gi] ? m[3] : 0.0f);
                *(float4*)(pp + 4) = make_float4(anyv[gi] ? m[4] : 0.0f, anyv[gi] ? m[5] : 0.0f,
                                                 anyv[gi] ? m[6] : 0.0f, anyv[gi] ? m[7] : 0.0f);
            }
        }
        __syncthreads();

        // ================= Layer 2: 128 -> 64 =================
        float c[GPP][8];
        {
            float2 wp[8];
            #pragma unroll
            for (int hh = 0; hh < 8; hh++)
                wp[hh] = *(const float2*)(W2ps + (hbase + hh) * 64 + 2 * lane);
            #pragma unroll
            for (int gi = 0; gi < GPP; gi++) {
                float2 pp = *(const float2*)(pl1 + gi * 64 + 2 * lane);
                #pragma unroll
                for (int hh = 0; hh < 8; hh++)
                    c[gi][hh] = warp_sum_f32(pp.x * wp[hh].x + pp.y * wp[hh].y) + b2s[hbase + hh];
            }
        }
        #pragma unroll
        for (int half = 0; half < 2; half++) {
            const int hoff = half * 4;
            unsigned long long acc2[GPP][4];
            if (half == 0) { JSWEEP(cW2h, bufA, 0, acc2, c); }
            else           { JSWEEP(cW2h, bufA, 4, acc2, c); }
            #pragma unroll
            for (int gi = 0; gi < GPP; gi++) {
                float o[4], m[4];
                #pragma unroll
                for (int hh = 0; hh < 4; hh++) {
                    float s = unpack_sum(acc2[gi][hh]);
                    float r = s > 0.0f ? s : NEG_SLOPE * s;
                    o[hh] = valid[gi] ? r : 0.0f;
                    m[hh] = warp_max_f32(valid[gi] ? r : -FLT_MAX);
                }
                *(float4*)(bufB + gi * (Vv * STRIDE) + lane * STRIDE + hbase + hoff)
                    = make_float4(o[0], o[1], o[2], o[3]);
                if (lane == 0)
                    *(float4*)(pl2 + gi * 64 + hbase + hoff)
                        = make_float4(anyv[gi] ? m[0] : 0.0f, anyv[gi] ? m[1] : 0.0f,
                                      anyv[gi] ? m[2] : 0.0f, anyv[gi] ? m[3] : 0.0f);
            }
        }
        __syncthreads();

        // ================= Layer 3: 128 -> 64 (pool only) =================
        {
            float2 wp[8];
            #pragma unroll
            for (int hh = 0; hh < 8; hh++)
                wp[hh] = *(const float2*)(W3ps + (hbase + hh) * 64 + 2 * lane);
            #pragma unroll
            for (int gi = 0; gi < GPP; gi++) {
                float2 pp = *(const float2*)(pl2 + gi * 64 + 2 * lane);
                #pragma unroll
                for (int hh = 0; hh < 8; hh++)
                    c[gi][hh] = warp_sum_f32(pp.x * wp[hh].x + pp.y * wp[hh].y) + b3s[hbase + hh];
            }
        }
        #pragma unroll
        for (int half = 0; half < 2; half++) {
            const int hoff = half * 4;
            unsigned long long acc2[GPP][4];
            if (half == 0) { JSWEEP(cW3h, bufB, 0, acc2, c); }
            else           { JSWEEP(cW3h, bufB, 4, acc2, c); }
            #pragma unroll
            for (int gi = 0; gi < GPP; gi++) {
                float m[4];
                #pragma unroll
                for (int hh = 0; hh < 4; hh++) {
                    float s = unpack_sum(acc2[gi][hh]);
                    float r = s > 0.0f ? s : NEG_SLOPE * s;
                    m[hh] = warp_max_f32(valid[gi] ? r : -FLT_MAX);
                }
                if (lane == 0)
                    *(float4*)(out + (size_t)(g0 + gi) * Hv + hbase + hoff)
                        = make_float4(anyv[gi] ? m[0] : 0.0f, anyv[gi] ? m[1] : 0.0f,
                                      anyv[gi] ? m[2] : 0.0f, anyv[gi] ? m[3] : 0.0f);
            }
        }
        // Cross-pass hazards: this pass's sync1 orders prev-pass L3 bufB reads
        // before this L2 bufB writes; prev sync2 orders prev L2 bufA reads
        // before this L1 bufA writes. Same invariant as R10.
    }
}

extern "C" void kernel_launch(void* const* d_in, const int* in_sizes, int n_in,
                              void* d_out, int out_size)
{
    const float* x  = (const float*)d_in[0];
    const void*  mk = d_in[1];
    const float* W1 = (const float*)d_in[2];
    const float* b1 = (const float*)d_in[3];
    const float* W2 = (const float*)d_in[4];
    const float* b2 = (const float*)d_in[5];
    const float* W3 = (const float*)d_in[6];
    const float* b3 = (const float*)d_in[7];
    float* out = (float*)d_out;

    // Copy out-halves (cols 0..63 of each 128-wide row) of W2/W3 into constant.
    void *p2, *p3;
    cudaGetSymbolAddress(&p2, cW2h);
    cudaGetSymbolAddress(&p3, cW3h);
    cudaMemcpy2DAsync(p2, 64 * sizeof(float), W2, 128 * sizeof(float),
                      64 * sizeof(float), 64, cudaMemcpyDeviceToDevice, 0);
    cudaMemcpy2DAsync(p3, 64 * sizeof(float), W3, 128 * sizeof(float),
                      64 * sizeof(float), 64, cudaMemcpyDeviceToDevice, 0);

    cudaFuncSetAttribute(fused_mlp_pool_kernel,
                         cudaFuncAttributeMaxDynamicSharedMemorySize, SMEM_BYTES);
    fused_mlp_pool_kernel<<<GRID, THREADS, SMEM_BYTES>>>(x, mk, W1, b1, W2, b2, W3, b3, out);
}

// round 12
// speedup vs baseline: 3.0944x; 3.0944x over previous
#include <cuda_runtime.h>
#include <cstdint>
#include <cfloat>

#define NEG_SLOPE 0.01f

constexpr int Vv = 32, Fv = 16, Hv = 64;
constexpr int NG = 32 * 512;         // 16384 groups
constexpr int GPP = 4;               // groups per pass (weight-load amortization)
constexpr int NPASS = NG / GPP;      // 4096
constexpr int THREADS = 256;
constexpr int STRIDE = 68;           // padded activation row stride (conflict-free LDS.128)
constexpr int GRID = 296;            // 2 blocks/SM * 148 SMs

// Shared float layout (107264 B -> 2 blocks/SM):
//  W1s [1024] | W2s [8192] | W3s [8192] | b1s,b2s,b3s [192] | pl1 [256] | pl2 [256]
//  buf [4*32*68 = 8704]  (single in-place activation buffer)
constexpr int OFF_W1  = 0;
constexpr int OFF_W2  = 1024;
constexpr int OFF_W3  = 9216;
constexpr int OFF_B1  = 17408;
constexpr int OFF_B2  = 17472;
constexpr int OFF_B3  = 17536;
constexpr int OFF_PL1 = 17600;
constexpr int OFF_PL2 = 17856;
constexpr int OFF_BUF = 18112;
constexpr int SMEM_FLOATS = 26816;
constexpr int SMEM_BYTES  = SMEM_FLOATS * 4;   // 107264

__device__ __forceinline__ float warp_max_f32(float v) {
    #pragma unroll
    for (int o = 16; o >= 1; o >>= 1)
        v = fmaxf(v, __shfl_xor_sync(0xffffffffu, v, o));
    return v;
}
__device__ __forceinline__ float warp_sum_f32(float v) {
    #pragma unroll
    for (int o = 16; o >= 1; o >>= 1)
        v += __shfl_xor_sync(0xffffffffu, v, o);
    return v;
}

__global__ __launch_bounds__(THREADS, 2)
void fused_mlp_pool_kernel(const float* __restrict__ x,
                           const void*  __restrict__ maskp,
                           const float* __restrict__ W1,
                           const float* __restrict__ b1,
                           const float* __restrict__ W2,
                           const float* __restrict__ b2,
                           const float* __restrict__ W3,
                           const float* __restrict__ b3,
                           float* __restrict__ out)
{
    extern __shared__ float sm[];
    float* W1s = sm + OFF_W1;
    float* W2s = sm + OFF_W2;
    float* W3s = sm + OFF_W3;
    float* b1s = sm + OFF_B1;
    float* b2s = sm + OFF_B2;
    float* b3s = sm + OFF_B3;
    float* pl1 = sm + OFF_PL1;      // [GPP][64]
    float* pl2 = sm + OFF_PL2;      // [GPP][64]
    float* buf = sm + OFF_BUF;      // [GPP][32][STRIDE], reused in place by L2

    const int tid  = threadIdx.x;
    const int lane = tid & 31;      // = v
    const int warp = tid >> 5;      // 0..7
    const int hbase = warp * 8;

    // ---- stage weights into shared ----
    for (int i = tid; i < 1024; i += THREADS) W1s[i] = W1[i];
    for (int i = tid; i < 8192; i += THREADS) W2s[i] = W2[i];
    for (int i = tid; i < 8192; i += THREADS) W3s[i] = W3[i];
    if (tid < 64) { b1s[tid] = b1[tid]; b2s[tid] = b2[tid]; b3s[tid] = b3[tid]; }

    // ---- detect mask encoding (bool-u8 / int32 / float32) ----
    __shared__ int s_flags[4];
    if (tid < 4) s_flags[tid] = 0;
    __syncthreads();
    {
        int f0 = 0, f1 = 0, f23 = 0;
        const unsigned char* mb = (const unsigned char*)maskp;
        #pragma unroll
        for (int i = 0; i < 16; i++) {
            int idx = tid * 16 + i;
            unsigned char c = mb[idx];
            if (c) { int m = idx & 3; if (m == 0) f0 = 1; else if (m == 1) f1 = 1; else f23 = 1; }
        }
        if (f0)  atomicOr(&s_flags[0], 1);
        if (f1)  atomicOr(&s_flags[1], 1);
        if (f23) atomicOr(&s_flags[2], 1);
    }
    __syncthreads();
    const int fmt = s_flags[1] ? 1 : (s_flags[0] ? 0 : (s_flags[2] ? 2 : 0));

    for (int pass = blockIdx.x; pass < NPASS; pass += gridDim.x) {
        const int g0 = pass * GPP;

        // ---- masks ----
        bool valid[GPP], anyv[GPP];
        #pragma unroll
        for (int gi = 0; gi < GPP; gi++) {
            const int midx = (g0 + gi) * Vv + lane;
            bool v;
            if (fmt == 1)      v = ((const unsigned char*)maskp)[midx] != 0;
            else if (fmt == 0) v = ((const int*)maskp)[midx] != 0;
            else               v = ((const float*)maskp)[midx] != 0.0f;
            valid[gi] = v;
            anyv[gi]  = __ballot_sync(0xffffffffu, v) != 0;
        }

        // ---- x rows ----
        float4 xr[GPP][4];
        #pragma unroll
        for (int gi = 0; gi < GPP; gi++) {
            const float4* xp = (const float4*)(x + ((size_t)(g0 + gi) * Vv + lane) * Fv);
            xr[gi][0] = xp[0]; xr[gi][1] = xp[1]; xr[gi][2] = xp[2]; xr[gi][3] = xp[3];
        }

        float acc[GPP][8];

        // ================= Layer 1: 16 -> 64 =================
        #pragma unroll 2
        for (int hh = 0; hh < 8; hh++) {
            const float4* w = (const float4*)(W1s + (hbase + hh) * 16);
            float4 w0 = w[0], w1 = w[1], w2 = w[2], w3 = w[3];
            const float bb = b1s[hbase + hh];
            #pragma unroll
            for (int gi = 0; gi < GPP; gi++) {
                float s = bb;
                s = fmaf(xr[gi][0].x, w0.x, s); s = fmaf(xr[gi][0].y, w0.y, s);
                s = fmaf(xr[gi][0].z, w0.z, s); s = fmaf(xr[gi][0].w, w0.w, s);
                s = fmaf(xr[gi][1].x, w1.x, s); s = fmaf(xr[gi][1].y, w1.y, s);
                s = fmaf(xr[gi][1].z, w1.z, s); s = fmaf(xr[gi][1].w, w1.w, s);
                s = fmaf(xr[gi][2].x, w2.x, s); s = fmaf(xr[gi][2].y, w2.y, s);
                s = fmaf(xr[gi][2].z, w2.z, s); s = fmaf(xr[gi][2].w, w2.w, s);
                s = fmaf(xr[gi][3].x, w3.x, s); s = fmaf(xr[gi][3].y, w3.y, s);
                s = fmaf(xr[gi][3].z, w3.z, s); s = fmaf(xr[gi][3].w, w3.w, s);
                acc[gi][hh] = s;
            }
        }
        // epilogue L1 -> buf, pl1
        #pragma unroll
        for (int gi = 0; gi < GPP; gi++) {
            float o[8], m[8];
            #pragma unroll
            for (int hh = 0; hh < 8; hh++) {
                float r = acc[gi][hh] > 0.0f ? acc[gi][hh] : NEG_SLOPE * acc[gi][hh];
                o[hh] = valid[gi] ? r : 0.0f;
                m[hh] = warp_max_f32(valid[gi] ? r : -FLT_MAX);
            }
            float* row = buf + gi * (Vv * STRIDE) + lane * STRIDE + hbase;
            *(float4*)(row)     = make_float4(o[0], o[1], o[2], o[3]);
            *(float4*)(row + 4) = make_float4(o[4], o[5], o[6], o[7]);
            if (lane == 0) {
                float* pp = pl1 + gi * 64 + hbase;
                *(float4*)(pp)     = make_float4(anyv[gi] ? m[0] : 0.0f, anyv[gi] ? m[1] : 0.0f,
                                                 anyv[gi] ? m[2] : 0.0f, anyv[gi] ? m[3] : 0.0f);
                *(float4*)(pp + 4) = make_float4(anyv[gi] ? m[4] : 0.0f, anyv[gi] ? m[5] : 0.0f,
                                                 anyv[gi] ? m[6] : 0.0f, anyv[gi] ? m[7] : 0.0f);
            }
        }
        __syncthreads();   // sync1: L1 writes -> L2 reads

        // ================= Layer 2: 128 -> 64 =================
        {   // pool-side constant: acc = b2[h] + sum_j pl1[j] * W2[h][64+j]
            float2 wp[8];
            #pragma unroll
            for (int hh = 0; hh < 8; hh++)
                wp[hh] = *(const float2*)(W2s + (hbase + hh) * 128 + 64 + 2 * lane);
            #pragma unroll
            for (int gi = 0; gi < GPP; gi++) {
                float2 pp = *(const float2*)(pl1 + gi * 64 + 2 * lane);
                #pragma unroll
                for (int hh = 0; hh < 8; hh++)
                    acc[gi][hh] = warp_sum_f32(pp.x * wp[hh].x + pp.y * wp[hh].y) + b2s[hbase + hh];
            }
        }
        #pragma unroll 2
        for (int j = 0; j < 64; j += 4) {
            float4 w[8];
            #pragma unroll
            for (int hh = 0; hh < 8; hh++)
                w[hh] = *(const float4*)(W2s + (hbase + hh) * 128 + j);
            float4 a[GPP];
            #pragma unroll
            for (int gi = 0; gi < GPP; gi++)
                a[gi] = *(const float4*)(buf + gi * (Vv * STRIDE) + lane * STRIDE + j);
            #pragma unroll
            for (int gi = 0; gi < GPP; gi++)
                #pragma unroll
                for (int hh = 0; hh < 8; hh++)
                    acc[gi][hh] = fmaf(a[gi].x, w[hh].x, fmaf(a[gi].y, w[hh].y,
                                  fmaf(a[gi].z, w[hh].z, fmaf(a[gi].w, w[hh].w, acc[gi][hh]))));
        }
        __syncthreads();   // sync2: L2 reads of buf complete before in-place writes

        // epilogue L2 -> buf (in place), pl2
        #pragma unroll
        for (int gi = 0; gi < GPP; gi++) {
            float o[8], m[8];
            #pragma unroll
            for (int hh = 0; hh < 8; hh++) {
                float r = acc[gi][hh] > 0.0f ? acc[gi][hh] : NEG_SLOPE * acc[gi][hh];
                o[hh] = valid[gi] ? r : 0.0f;
                m[hh] = warp_max_f32(valid[gi] ? r : -FLT_MAX);
            }
            float* row = buf + gi * (Vv * STRIDE) + lane * STRIDE + hbase;
            *(float4*)(row)     = make_float4(o[0], o[1], o[2], o[3]);
            *(float4*)(row + 4) = make_float4(o[4], o[5], o[6], o[7]);
            if (lane == 0) {
                float* pp = pl2 + gi * 64 + hbase;
                *(float4*)(pp)     = make_float4(anyv[gi] ? m[0] : 0.0f, anyv[gi] ? m[1] : 0.0f,
                                                 anyv[gi] ? m[2] : 0.0f, anyv[gi] ? m[3] : 0.0f);
                *(float4*)(pp + 4) = make_float4(anyv[gi] ? m[4] : 0.0f, anyv[gi] ? m[5] : 0.0f,
                                                 anyv[gi] ? m[6] : 0.0f, anyv[gi] ? m[7] : 0.0f);
            }
        }
        __syncthreads();   // sync3: L2 writes -> L3 reads

        // ================= Layer 3: 128 -> 64 (pool only) =================
        {
            float2 wp[8];
            #pragma unroll
            for (int hh = 0; hh < 8; hh++)
                wp[hh] = *(const float2*)(W3s + (hbase + hh) * 128 + 64 + 2 * lane);
            #pragma unroll
            for (int gi = 0; gi < GPP; gi++) {
                float2 pp = *(const float2*)(pl2 + gi * 64 + 2 * lane);
                #pragma unroll
                for (int hh = 0; hh < 8; hh++)
                    acc[gi][hh] = warp_sum_f32(pp.x * wp[hh].x + pp.y * wp[hh].y) + b3s[hbase + hh];
            }
        }
        #pragma unroll 2
        for (int j = 0; j < 64; j += 4) {
            float4 w[8];
            #pragma unroll
            for (int hh = 0; hh < 8; hh++)
                w[hh] = *(const float4*)(W3s + (hbase + hh) * 128 + j);
            float4 a[GPP];
            #pragma unroll
            for (int gi = 0; gi < GPP; gi++)
                a[gi] = *(const float4*)(buf + gi * (Vv * STRIDE) + lane * STRIDE + j);
            #pragma unroll
            for (int gi = 0; gi < GPP; gi++)
                #pragma unroll
                for (int hh = 0; hh < 8; hh++)
                    acc[gi][hh] = fmaf(a[gi].x, w[hh].x, fmaf(a[gi].y, w[hh].y,
                                  fmaf(a[gi].z, w[hh].z, fmaf(a[gi].w, w[hh].w, acc[gi][hh]))));
        }
        // final epilogue: pool3 -> out
        #pragma unroll
        for (int gi = 0; gi < GPP; gi++) {
            float m[8];
            #pragma unroll
            for (int hh = 0; hh < 8; hh++) {
                float r = acc[gi][hh] > 0.0f ? acc[gi][hh] : NEG_SLOPE * acc[gi][hh];
                m[hh] = warp_max_f32(valid[gi] ? r : -FLT_MAX);
            }
            if (lane == 0) {
                float* op = out + (size_t)(g0 + gi) * Hv + hbase;
                *(float4*)(op)     = make_float4(anyv[gi] ? m[0] : 0.0f, anyv[gi] ? m[1] : 0.0f,
                                                 anyv[gi] ? m[2] : 0.0f, anyv[gi] ? m[3] : 0.0f);
                *(float4*)(op + 4) = make_float4(anyv[gi] ? m[4] : 0.0f, anyv[gi] ? m[5] : 0.0f,
                                                 anyv[gi] ? m[6] : 0.0f, anyv[gi] ? m[7] : 0.0f);
            }
        }
        __syncthreads();   // sync4: L3 reads of buf complete before next pass's L1 writes
    }
}

extern "C" void kernel_launch(void* const* d_in, const int* in_sizes, int n_in,
                              void* d_out, int out_size)
{
    const float* x  = (const float*)d_in[0];
    const void*  mk = d_in[1];
    const float* W1 = (const float*)d_in[2];
    const float* b1 = (const float*)d_in[3];
    const float* W2 = (const float*)d_in[4];
    const float* b2 = (const float*)d_in[5];
    const float* W3 = (const float*)d_in[6];
    const float* b3 = (const float*)d_in[7];
    float* out = (float*)d_out;

    cudaFuncSetAttribute(fused_mlp_pool_kernel,
                         cudaFuncAttributeMaxDynamicSharedMemorySize, SMEM_BYTES);
    fused_mlp_pool_kernel<<<GRID, THREADS, SMEM_BYTES>>>(x, mk, W1, b1, W2, b2, W3, b3, out);
}